// round 16
// baseline (speedup 1.0000x reference)
#include <cuda_runtime.h>
#include <cuda_bf16.h>
#include <cstdint>

// DeltaNet fused recurrent decode step (all buffers float32; bf16 rounding
// emulated to match the reference exactly).
//   s1  = bf16(exp(gate) * state) ; acc = k^T s1 ; delta = beta*(v - acc)
//   s2  = bf16(s1 + k (outer) delta) ; out = bf16(q^T s2)
//
// PERSISTENT version: grid = 6 CTAs/SM x 148 SMs = 888; each CTA loops over
// ~7 (b,h) heads. After pass 1 of head h, the CTA issues prefetch.global.L2
// for head h+888's 64KB state tile, so DRAM streams the next tile while
// pass 2 runs entirely out of smem. Warp g owns dk rows [16g,16g+16); lane
// covers 4 dv columns; pass-1 loads batched 4-deep (MLP).

static __device__ __forceinline__ float bf16r(float x) {
    return __bfloat162float(__float2bfloat16(x));
}

static constexpr int D = 128;

__global__ void __launch_bounds__(256)
deltanet_persist(const float* __restrict__ q,
                 const float* __restrict__ k,
                 const float* __restrict__ v,
                 const float* __restrict__ beta,
                 const float* __restrict__ gate,
                 const float* __restrict__ state,
                 float* __restrict__ out,
                 int BH)
{
    __shared__ __align__(16) __nv_bfloat16 s1sm[D * D];  // 32 KB decayed state
    __shared__ float ksm[D];
    __shared__ float qsm[D];
    __shared__ __align__(16) float red[8][D];            // 4 KB cross-warp partials

    const int t   = threadIdx.x;
    const int g   = t >> 5;       // warp: dk rows [16g, 16g+16)
    const int c   = t & 31;
    const int col = 4 * c;        // 4 dv columns per lane
    const int dk0 = g * 16;
    const float* kp = ksm + dk0;

    for (int bh = blockIdx.x; bh < BH; bh += gridDim.x) {
        const float* st = state + (size_t)bh * (D * D);

        __syncthreads();          // prev head's warp-0 output/red reads done
        if (t < D) {
            ksm[t] = __ldg(k + (size_t)bh * D + t);
            qsm[t] = __ldg(q + (size_t)bh * D + t);
        }
        const float decay = expf(__ldg(gate + bh));
        const float betaf = __ldg(beta + bh);
        __syncthreads();

        // ---- Pass 1: s1 = bf16(decay*S) -> smem; acc = k^T s1 ----
        float acc0 = 0.f, acc1 = 0.f, acc2 = 0.f, acc3 = 0.f;

        const float4* p = reinterpret_cast<const float4*>(st + (size_t)dk0 * D) + c;
        __nv_bfloat16* s1p = s1sm + dk0 * D + col;

#pragma unroll
        for (int b = 0; b < 4; ++b) {
            // 4 independent streaming loads (forced MLP)
            const float4 f0 = __ldcs(p);
            const float4 f1 = __ldcs(p + 32);
            const float4 f2 = __ldcs(p + 64);
            const float4 f3 = __ldcs(p + 96);
            p += 128;

            float4 fr[4] = {f0, f1, f2, f3};
#pragma unroll
            for (int r = 0; r < 4; ++r) {
                const float4 f = fr[r];
                const __nv_bfloat162 p01 =
                    __float22bfloat162_rn(make_float2(f.x * decay, f.y * decay));
                const __nv_bfloat162 p23 =
                    __float22bfloat162_rn(make_float2(f.z * decay, f.w * decay));

                uint2 pk;
                pk.x = *reinterpret_cast<const uint32_t*>(&p01);
                pk.y = *reinterpret_cast<const uint32_t*>(&p23);
                *reinterpret_cast<uint2*>(s1p) = pk;
                s1p += D;

                const float kf = kp[4 * b + r];
                acc0 += kf * __low2float(p01);
                acc1 += kf * __high2float(p01);
                acc2 += kf * __low2float(p23);
                acc3 += kf * __high2float(p23);
            }
        }

        *reinterpret_cast<float4*>(&red[g][col]) = make_float4(acc0, acc1, acc2, acc3);
        __syncthreads();

        float delta[4];
#pragma unroll
        for (int j = 0; j < 4; ++j) {
            float a = 0.f;
#pragma unroll
            for (int w = 0; w < 8; ++w) a += red[w][col + j];
            const float vf = __ldg(v + (size_t)bh * D + col + j);
            delta[j] = betaf * (vf - a);
        }

        // ---- L2 prefetch of the NEXT head's state (overlaps pass 2) ----
        const int nbh = bh + gridDim.x;
        if (nbh < BH) {
            const char* np = reinterpret_cast<const char*>(state + (size_t)nbh * (D * D));
            asm volatile("prefetch.global.L2 [%0];" :: "l"(np + t * 256));
            asm volatile("prefetch.global.L2 [%0];" :: "l"(np + t * 256 + 128));
        }
        __syncthreads();   // red consumed before pass-2 overwrites it

        // ---- Pass 2: out = q^T bf16(s1 + k*delta), s1 from smem ----
        float o0 = 0.f, o1 = 0.f, o2 = 0.f, o3 = 0.f;

        const __nv_bfloat16* s1r = s1sm + dk0 * D + col;
#pragma unroll 8
        for (int i = 0; i < 16; ++i) {
            const uint2 pk = *reinterpret_cast<const uint2*>(s1r);
            s1r += D;
            __nv_bfloat162 p01, p23;
            *reinterpret_cast<uint32_t*>(&p01) = pk.x;
            *reinterpret_cast<uint32_t*>(&p23) = pk.y;

            const float kf = kp[i];
            const float qf = qsm[dk0 + i];

            // paired bf16 rounding: one CVT packs two RN-rounded halves
            const __nv_bfloat162 r01 = __float22bfloat162_rn(
                make_float2(__low2float(p01)  + kf * delta[0],
                            __high2float(p01) + kf * delta[1]));
            const __nv_bfloat162 r23 = __float22bfloat162_rn(
                make_float2(__low2float(p23)  + kf * delta[2],
                            __high2float(p23) + kf * delta[3]));

            o0 += qf * __low2float(r01);
            o1 += qf * __high2float(r01);
            o2 += qf * __low2float(r23);
            o3 += qf * __high2float(r23);
        }

        *reinterpret_cast<float4*>(&red[g][col]) = make_float4(o0, o1, o2, o3);
        __syncthreads();

        // warp 0 reduces and writes f32 output (bf16-rounded)
        if (g == 0) {
            float s[4];
#pragma unroll
            for (int j = 0; j < 4; ++j) {
                float r = 0.f;
#pragma unroll
                for (int w = 0; w < 8; ++w) r += red[w][col + j];
                s[j] = bf16r(r);
            }
            *reinterpret_cast<float4*>(out + (size_t)bh * D + col) =
                make_float4(s[0], s[1], s[2], s[3]);
        }
    }
}

// ---------------- Generic fallback: runtime DK, DV ----------------
__global__ void __launch_bounds__(128)
deltanet_f32_gen(const float* __restrict__ q,
                 const float* __restrict__ k,
                 const float* __restrict__ v,
                 const float* __restrict__ beta,
                 const float* __restrict__ gate,
                 const float* __restrict__ state,
                 float* __restrict__ out,
                 int DK, int DV)
{
    extern __shared__ float dyn[];   // ks[DK], qs[DK]
    float* ks = dyn;
    float* qs = dyn + DK;

    const int bh = blockIdx.x;
    const int t  = threadIdx.x;

    for (int i = t; i < DK; i += 128) {
        ks[i] = __ldg(k + (size_t)bh * DK + i);
        qs[i] = __ldg(q + (size_t)bh * DK + i);
    }
    __syncthreads();

    const float decay = expf(__ldg(gate + bh));
    const float betaf = __ldg(beta + bh);
    const float* S = state + (size_t)bh * DK * DV;

    for (int j = t; j < DV; j += 128) {
        float acc = 0.0f;
        for (int dk = 0; dk < DK; ++dk)
            acc += ks[dk] * bf16r(__ldg(S + (size_t)dk * DV + j) * decay);

        const float delta = betaf * (__ldg(v + (size_t)bh * DV + j) - acc);

        float o = 0.0f;
        for (int dk = 0; dk < DK; ++dk) {
            const float s1 = bf16r(__ldg(S + (size_t)dk * DV + j) * decay);
            o += qs[dk] * bf16r(s1 + ks[dk] * delta);
        }
        out[(size_t)bh * DV + j] = bf16r(o);
    }
}

extern "C" void kernel_launch(void* const* d_in, const int* in_sizes, int n_in,
                              void* d_out, int out_size)
{
    // Insertion order (q, k, v, beta, gate, state); element counts; all f32.
    const float* q     = (const float*)d_in[0];
    const float* k     = (const float*)d_in[1];
    const float* v     = (const float*)d_in[2];
    const float* beta  = (const float*)d_in[3];
    const float* gate  = (const float*)d_in[4];
    const float* state = (const float*)d_in[5];
    float* out = (float*)d_out;

    const long long BH = in_sizes[3];                 // |beta| = B*H
    const long long DK = (long long)in_sizes[0] / BH; // |q| / BH
    const long long DV = (long long)in_sizes[2] / BH; // |v| / BH

    if (DK == 128 && DV == 128) {
        const int grid = 888;  // 6 resident CTAs/SM x 148 SMs
        deltanet_persist<<<grid, 256>>>(q, k, v, beta, gate, state, out, (int)BH);
    } else {
        const size_t shmem = (size_t)(2 * DK) * sizeof(float);
        deltanet_f32_gen<<<(unsigned)BH, 128, shmem>>>(
            q, k, v, beta, gate, state, out, (int)DK, (int)DV);
    }
}

// round 17
// speedup vs baseline: 1.1534x; 1.1534x over previous
#include <cuda_runtime.h>
#include <cuda_bf16.h>
#include <cstdint>

// DeltaNet fused recurrent decode step (all buffers float32; bf16 rounding
// emulated to match the reference exactly).
//   s1  = bf16(exp(gate) * state) ; acc = k^T s1 ; delta = beta*(v - acc)
//   s2  = bf16(s1 + k (outer) delta) ; out = bf16(q^T s2)
//
// One CTA (256 threads, 8 warps) per (b,h): warp g owns dk rows [16g,16g+16),
// lane covers 4 dv columns. s1 is REGISTER-RESIDENT (16 packed bf16x2 pairs
// per thread) — pass 2 never touches smem for state, so the DRAM-idle window
// per head shrinks ~2x. Pass-1 loads batched 4-deep (MLP). smem: 5.5 KB.

static __device__ __forceinline__ float bf16r(float x) {
    return __bfloat162float(__float2bfloat16(x));
}

static constexpr int D = 128;

__global__ void __launch_bounds__(256, 3)
deltanet_reg_256(const float* __restrict__ q,
                 const float* __restrict__ k,
                 const float* __restrict__ v,
                 const float* __restrict__ beta,
                 const float* __restrict__ gate,
                 const float* __restrict__ state,
                 float* __restrict__ out)
{
    __shared__ float ksm[D];
    __shared__ float qsm[D];
    __shared__ __align__(16) float red[8][D];   // 4 KB cross-warp partials

    const int t   = threadIdx.x;
    const int g   = t >> 5;       // warp: dk rows [16g, 16g+16)
    const int c   = t & 31;
    const int col = 4 * c;        // 4 dv columns per lane
    const int dk0 = g * 16;
    const int bh  = blockIdx.x;

    const float* st = state + (size_t)bh * (D * D);

    if (t < D) {
        ksm[t] = __ldg(k + (size_t)bh * D + t);
        qsm[t] = __ldg(q + (size_t)bh * D + t);
    }
    const float decay = expf(__ldg(gate + bh));
    const float betaf = __ldg(beta + bh);
    __syncthreads();

    // ---- Pass 1: s1 = bf16(decay*S) -> REGISTERS; acc = k^T s1 ----
    uint32_t s1a[16];             // packed bf16x2: cols (0,1) of each row
    uint32_t s1b[16];             // packed bf16x2: cols (2,3) of each row
    float acc0 = 0.f, acc1 = 0.f, acc2 = 0.f, acc3 = 0.f;

    const float4* p = reinterpret_cast<const float4*>(st + (size_t)dk0 * D) + c;

#pragma unroll
    for (int b = 0; b < 4; ++b) {
        // 4 independent streaming loads (forced MLP)
        const float4 f0 = __ldcs(p);
        const float4 f1 = __ldcs(p + 32);
        const float4 f2 = __ldcs(p + 64);
        const float4 f3 = __ldcs(p + 96);
        p += 128;

        float4 fr[4] = {f0, f1, f2, f3};
#pragma unroll
        for (int r = 0; r < 4; ++r) {
            const int i = 4 * b + r;
            const float4 f = fr[r];
            // bf16 round-to-nearest-even after decay (reference stores s1 bf16)
            const __nv_bfloat162 p01 =
                __float22bfloat162_rn(make_float2(f.x * decay, f.y * decay));
            const __nv_bfloat162 p23 =
                __float22bfloat162_rn(make_float2(f.z * decay, f.w * decay));

            s1a[i] = *reinterpret_cast<const uint32_t*>(&p01);
            s1b[i] = *reinterpret_cast<const uint32_t*>(&p23);

            const float kf = ksm[dk0 + i];
            acc0 += kf * __low2float(p01);
            acc1 += kf * __high2float(p01);
            acc2 += kf * __low2float(p23);
            acc3 += kf * __high2float(p23);
        }
    }

    *reinterpret_cast<float4*>(&red[g][col]) = make_float4(acc0, acc1, acc2, acc3);
    __syncthreads();

    float delta[4];
#pragma unroll
    for (int j = 0; j < 4; ++j) {
        float a = 0.f;
#pragma unroll
        for (int w = 0; w < 8; ++w) a += red[w][col + j];
        const float vf = __ldg(v + (size_t)bh * D + col + j);
        delta[j] = betaf * (vf - a);
    }
    __syncthreads();   // red consumed before pass-2 overwrites it

    // ---- Pass 2: out = q^T bf16(s1 + k*delta), s1 from REGISTERS ----
    float o0 = 0.f, o1 = 0.f, o2 = 0.f, o3 = 0.f;

#pragma unroll
    for (int i = 0; i < 16; ++i) {
        __nv_bfloat162 p01, p23;
        *reinterpret_cast<uint32_t*>(&p01) = s1a[i];
        *reinterpret_cast<uint32_t*>(&p23) = s1b[i];

        const float kf = ksm[dk0 + i];
        const float qf = qsm[dk0 + i];

        // paired bf16 rounding of s2 (one CVT per 2 elements, RN per half)
        const __nv_bfloat162 r01 = __float22bfloat162_rn(
            make_float2(__low2float(p01)  + kf * delta[0],
                        __high2float(p01) + kf * delta[1]));
        const __nv_bfloat162 r23 = __float22bfloat162_rn(
            make_float2(__low2float(p23)  + kf * delta[2],
                        __high2float(p23) + kf * delta[3]));

        o0 += qf * __low2float(r01);
        o1 += qf * __high2float(r01);
        o2 += qf * __low2float(r23);
        o3 += qf * __high2float(r23);
    }

    *reinterpret_cast<float4*>(&red[g][col]) = make_float4(o0, o1, o2, o3);
    __syncthreads();

    // warp 0 reduces and writes f32 output (bf16-rounded, matching reference)
    if (g == 0) {
        float s[4];
#pragma unroll
        for (int j = 0; j < 4; ++j) {
            float r = 0.f;
#pragma unroll
            for (int w = 0; w < 8; ++w) r += red[w][col + j];
            s[j] = bf16r(r);
        }
        *reinterpret_cast<float4*>(out + (size_t)bh * D + col) =
            make_float4(s[0], s[1], s[2], s[3]);
    }
}

// ---------------- Generic fallback: runtime DK, DV ----------------
__global__ void __launch_bounds__(128)
deltanet_f32_gen(const float* __restrict__ q,
                 const float* __restrict__ k,
                 const float* __restrict__ v,
                 const float* __restrict__ beta,
                 const float* __restrict__ gate,
                 const float* __restrict__ state,
                 float* __restrict__ out,
                 int DK, int DV)
{
    extern __shared__ float dyn[];   // ks[DK], qs[DK]
    float* ks = dyn;
    float* qs = dyn + DK;

    const int bh = blockIdx.x;
    const int t  = threadIdx.x;

    for (int i = t; i < DK; i += 128) {
        ks[i] = __ldg(k + (size_t)bh * DK + i);
        qs[i] = __ldg(q + (size_t)bh * DK + i);
    }
    __syncthreads();

    const float decay = expf(__ldg(gate + bh));
    const float betaf = __ldg(beta + bh);
    const float* S = state + (size_t)bh * DK * DV;

    for (int j = t; j < DV; j += 128) {
        float acc = 0.0f;
        for (int dk = 0; dk < DK; ++dk)
            acc += ks[dk] * bf16r(__ldg(S + (size_t)dk * DV + j) * decay);

        const float delta = betaf * (__ldg(v + (size_t)bh * DV + j) - acc);

        float o = 0.0f;
        for (int dk = 0; dk < DK; ++dk) {
            const float s1 = bf16r(__ldg(S + (size_t)dk * DV + j) * decay);
            o += qs[dk] * bf16r(s1 + ks[dk] * delta);
        }
        out[(size_t)bh * DV + j] = bf16r(o);
    }
}

extern "C" void kernel_launch(void* const* d_in, const int* in_sizes, int n_in,
                              void* d_out, int out_size)
{
    // Insertion order (q, k, v, beta, gate, state); element counts; all f32.
    const float* q     = (const float*)d_in[0];
    const float* k     = (const float*)d_in[1];
    const float* v     = (const float*)d_in[2];
    const float* beta  = (const float*)d_in[3];
    const float* gate  = (const float*)d_in[4];
    const float* state = (const float*)d_in[5];
    float* out = (float*)d_out;

    const long long BH = in_sizes[3];                 // |beta| = B*H
    const long long DK = (long long)in_sizes[0] / BH; // |q| / BH
    const long long DV = (long long)in_sizes[2] / BH; // |v| / BH

    if (DK == 128 && DV == 128) {
        deltanet_reg_256<<<(unsigned)BH, 256>>>(q, k, v, beta, gate, state, out);
    } else {
        const size_t shmem = (size_t)(2 * DK) * sizeof(float);
        deltanet_f32_gen<<<(unsigned)BH, 128, shmem>>>(
            q, k, v, beta, gate, state, out, (int)DK, (int)DV);
    }
}